// round 8
// baseline (speedup 1.0000x reference)
#include <cuda_runtime.h>
#include <cuda_bf16.h>
#include <stdint.h>

#define NROWS 131072
#define DD    128
#define RR    5
#define WW    16
#define TILE  128
#define NBLK  (NROWS/TILE)
#define NTHR  256

#define E1S   132      // float stride for e1 tile (row-major)
#define AST   144      // byte stride for int8 A rows (conflict-free quads)

// dynamic smem layout (bytes)
#define SM_A0    0
#define SM_A1    18432
#define SM_SA    36864
#define SM_SB    37376
#define SM_B     40960
#define SM_BSZ   32768
#define SM_E1    106496
#define SM_LOG   174080
#define SM_LOSS  179200
#define SM_TOTAL 179712

#define INV254 (1.0f/254.0f)

__device__ __align__(256) uint32_t g_B[RR * 8192];  // fragment-ordered int8 B, 2 levels
__device__ float g_sb[RR * DD];                     // per-(r, d-column) scales
__device__ float g_partial[NBLK];

// ---------------------------------------------------------------------------
__device__ __forceinline__ uint32_t smem_u32(const void* p) {
    uint32_t a;
    asm("{ .reg .u64 t; cvta.to.shared.u64 t, %1; cvt.u32.u64 %0, t; }" : "=r"(a) : "l"(p));
    return a;
}
__device__ __forceinline__ void cp16(uint32_t dst, const void* src) {
    asm volatile("cp.async.cg.shared.global [%0], [%1], 16;" :: "r"(dst), "l"(src));
}
#define CP_COMMIT() asm volatile("cp.async.commit_group;" ::: "memory")
#define CP_WAIT(N)  asm volatile("cp.async.wait_group %0;" :: "n"(N) : "memory")

#define LDSU32(r, a) asm volatile("ld.shared.b32 %0, [%1];" : "=r"(r) : "r"(a))
#define LDSV2(r0, r1, a) \
    asm volatile("ld.shared.v2.b32 {%0,%1}, [%2];" : "=r"(r0), "=r"(r1) : "r"(a))

#define IMMA16832(D, A, B0, B1) \
    asm volatile("mma.sync.aligned.m16n8k32.row.col.s32.s8.s8.s32 " \
        "{%0,%1,%2,%3},{%4,%5,%6,%7},{%8,%9},{%0,%1,%2,%3};" \
        : "+r"((D)[0]), "+r"((D)[1]), "+r"((D)[2]), "+r"((D)[3]) \
        : "r"((A)[0]), "r"((A)[1]), "r"((A)[2]), "r"((A)[3]), "r"(B0), "r"(B1))

__device__ __forceinline__ uint32_t pack4(int a, int b, int c, int d) {
    return (uint32_t)(a & 255) | ((uint32_t)(b & 255) << 8) |
           ((uint32_t)(c & 255) << 16) | ((uint32_t)(d & 255) << 24);
}

// ---------------------------------------------------------------------------
// prep: one block per (r, d): C_r[d][e] = sum_w ws[w,r]*rel[w][d][e];
// per-column scale s_b = max_e|C|/127; two-level int8 quantize; write
// fragment-ordered so the main kernel's B loads are plain ld.shared.v2.
// ---------------------------------------------------------------------------
__global__ void prep_kernel(const float* __restrict__ rel, const float* __restrict__ ws) {
    const int blk = blockIdx.x;            // 0..639
    const int r = blk >> 7;
    const int d = blk & 127;
    const int t = threadIdx.x;             // e4 = t, covers e = 4t..4t+3

    float c[4];
#pragma unroll
    for (int j = 0; j < 4; ++j) c[j] = 0.f;
#pragma unroll
    for (int w = 0; w < WW; ++w) {
        const float s = ws[w * RR + r];
        const float* p = rel + (size_t)w * DD * DD + d * DD + t * 4;
#pragma unroll
        for (int j = 0; j < 4; ++j) c[j] = fmaf(s, p[j], c[j]);
    }
    float mx = fmaxf(fmaxf(fabsf(c[0]), fabsf(c[1])), fmaxf(fabsf(c[2]), fabsf(c[3])));
#pragma unroll
    for (int off = 16; off > 0; off >>= 1)
        mx = fmaxf(mx, __shfl_xor_sync(0xffffffffu, mx, off));
    const float sb = fmaxf(mx, 1e-20f) / 127.f;
    if (t == 0) g_sb[r * DD + d] = sb;
    const float inv = 1.f / sb;

    int hi[4], lo[4];
#pragma unroll
    for (int j = 0; j < 4; ++j) {
        float q = c[j] * inv;
        int h = __float2int_rn(q);
        int l = __float2int_rn((q - (float)h) * 254.f);
        hi[j] = h; lo[j] = l;
    }
    const uint32_t phi = pack4(hi[0], hi[1], hi[2], hi[3]);
    const uint32_t plo = pack4(lo[0], lo[1], lo[2], lo[3]);

    // fragment ordering: u32 index = (((r*2+lvl)*16 + n8)*4 + kb)*64 + lane*2 + reg
    const int kb = t >> 3, eb4 = t & 7, reg = eb4 >> 2;
    const int lane = (d & 7) * 4 + (eb4 & 3);
    const int n8 = d >> 3;
    g_B[(((r * 2 + 0) * 16 + n8) * 4 + kb) * 64 + lane * 2 + reg] = phi;
    g_B[(((r * 2 + 1) * 16 + n8) * 4 + kb) * 64 + lane * 2 + reg] = plo;
}

// ---------------------------------------------------------------------------
__device__ __forceinline__ void load_B_stage(uint32_t sb_, int tid, int st) {
    const char* src = (const char*)g_B + (size_t)st * 32768;
    uint32_t dbase = sb_ + SM_B + (uint32_t)(st & 1) * SM_BSZ;
#pragma unroll
    for (int j = 0; j < 8; ++j) {
        int i = tid + j * NTHR;            // 0..2047 16B chunks
        cp16(dbase + i * 16, src + i * 16);
    }
}

__global__ __launch_bounds__(NTHR, 1) void bilinear_imma_kernel(
    const float* __restrict__ e1g, const float* __restrict__ e2g,
    const int* __restrict__ rels, float* __restrict__ preds) {

    extern __shared__ char smem[];
    const uint32_t sb = smem_u32(smem);
    const int tid  = threadIdx.x;
    const int lane = tid & 31;
    const int wid  = tid >> 5;
    const int n0   = blockIdx.x * TILE;

    // prefetch B stage 0
    load_B_stage(sb, tid, 0);
    CP_COMMIT();

    // s_b table -> smem
    float* ssb = (float*)(smem + SM_SB);
    for (int i = tid; i < RR * DD; i += NTHR) ssb[i] = g_sb[i];

    // --- A build: two-level int8 quantize of E2 tile (per-row scale) -------
    {
        const int row = tid >> 1, half = tid & 1;
        const float4* e2r = (const float4*)(e2g + (size_t)(n0 + row) * DD) + half * 16;
        float mx = 0.f;
#pragma unroll
        for (int q = 0; q < 16; ++q) {
            float4 t = e2r[q];
            mx = fmaxf(mx, fmaxf(fmaxf(fabsf(t.x), fabsf(t.y)), fmaxf(fabsf(t.z), fabsf(t.w))));
        }
        mx = fmaxf(mx, __shfl_xor_sync(0xffffffffu, mx, 1));
        const float sa = fmaxf(mx, 1e-20f) / 127.f;
        const float inv = 1.f / sa;
        float* ssa = (float*)(smem + SM_SA);
        if (!half) ssa[row] = sa;
        char* pA0 = smem + SM_A0 + row * AST + half * 64;
        char* pA1 = smem + SM_A1 + row * AST + half * 64;
#pragma unroll
        for (int q = 0; q < 16; ++q) {
            float4 t = e2r[q];
            float qx = t.x * inv, qy = t.y * inv, qz = t.z * inv, qw = t.w * inv;
            int h0 = __float2int_rn(qx), h1 = __float2int_rn(qy);
            int h2 = __float2int_rn(qz), h3 = __float2int_rn(qw);
            int l0 = __float2int_rn((qx - (float)h0) * 254.f);
            int l1 = __float2int_rn((qy - (float)h1) * 254.f);
            int l2 = __float2int_rn((qz - (float)h2) * 254.f);
            int l3 = __float2int_rn((qw - (float)h3) * 254.f);
            *(uint32_t*)(pA0 + q * 4) = pack4(h0, h1, h2, h3);
            *(uint32_t*)(pA1 + q * 4) = pack4(l0, l1, l2, l3);
        }
        // e1 tile -> smem row-major
        const float4* e1r = (const float4*)(e1g + (size_t)(n0 + row) * DD) + half * 16;
        float4* d1 = (float4*)((float*)(smem + SM_E1) + row * E1S) + half * 16;
#pragma unroll
        for (int q = 0; q < 16; ++q) d1[q] = e1r[q];
    }
    __syncthreads();

    // warp tile: rows [(wid>>1)*32, +32), cols [(wid&1)*64, +64)
    const int rowbase = (wid >> 1) * 32;
    const int chalf   = (wid & 1) * 64;
    const uint32_t aBase = sb + SM_A0 + (uint32_t)(rowbase + (lane >> 2)) * AST + (lane & 3) * 4;
    const uint32_t bWarp = (uint32_t)(wid & 1) * 8192 + (uint32_t)lane * 8;

    int acc_hi[2][8][4], acc_mid[2][8][4];
#pragma unroll
    for (int mb = 0; mb < 2; ++mb)
#pragma unroll
        for (int n8 = 0; n8 < 8; ++n8)
#pragma unroll
            for (int q = 0; q < 4; ++q) { acc_hi[mb][n8][q] = 0; acc_mid[mb][n8][q] = 0; }

    float* slog = (float*)(smem + SM_LOG);
    const float* se1 = (const float*)(smem + SM_E1);
    const float* ssa = (const float*)(smem + SM_SA);

    for (int r = 0; r < RR; ++r) {
        if (r < RR - 1) {
            load_B_stage(sb, tid, r + 1);
            CP_COMMIT();
            CP_WAIT(1);
        } else {
            CP_WAIT(0);
        }
        __syncthreads();

        const uint32_t bb = sb + SM_B + (uint32_t)(r & 1) * SM_BSZ + bWarp;

#pragma unroll
        for (int kb = 0; kb < 4; ++kb) {
            uint32_t ahi[2][4], alo[2][4];
#pragma unroll
            for (int mb = 0; mb < 2; ++mb) {
                const uint32_t ab = aBase + mb * (16 * AST) + kb * 32;
                LDSU32(ahi[mb][0], ab);
                LDSU32(ahi[mb][1], ab + 8 * AST);
                LDSU32(ahi[mb][2], ab + 16);
                LDSU32(ahi[mb][3], ab + 8 * AST + 16);
                LDSU32(alo[mb][0], ab + 18432);
                LDSU32(alo[mb][1], ab + 18432 + 8 * AST);
                LDSU32(alo[mb][2], ab + 18432 + 16);
                LDSU32(alo[mb][3], ab + 18432 + 8 * AST + 16);
            }
#pragma unroll
            for (int n8 = 0; n8 < 8; ++n8) {
                uint32_t bh0, bh1, bl0, bl1;
                const uint32_t ba = bb + (uint32_t)(n8 * 4 + kb) * 256;
                LDSV2(bh0, bh1, ba);
                LDSV2(bl0, bl1, ba + 16384);
#pragma unroll
                for (int mb = 0; mb < 2; ++mb) {
                    IMMA16832(acc_hi[mb][n8],  ahi[mb], bh0, bh1);
                    IMMA16832(acc_mid[mb][n8], ahi[mb], bl0, bl1);
                    IMMA16832(acc_mid[mb][n8], alo[mb], bh0, bh1);
                }
            }
        }

        // epilogue for this r: dequant + dot with e1, per-row scale folded out
        const float* sbp = ssb + r * DD + chalf + (lane & 3) * 2;
#pragma unroll
        for (int mb = 0; mb < 2; ++mb)
#pragma unroll
            for (int rs = 0; rs < 2; ++rs) {
                const int row = rowbase + mb * 16 + rs * 8 + (lane >> 2);
                const float sa = ssa[row];
                const float* er = se1 + row * E1S + chalf + (lane & 3) * 2;
                float s = 0.f;
#pragma unroll
                for (int n8 = 0; n8 < 8; ++n8) {
                    float2 u  = *(const float2*)(er  + n8 * 8);
                    float2 sv = *(const float2*)(sbp + n8 * 8);
                    const int q0 = rs * 2;
                    float v0 = (float)acc_hi[mb][n8][q0]     + (float)acc_mid[mb][n8][q0]     * INV254;
                    float v1 = (float)acc_hi[mb][n8][q0 + 1] + (float)acc_mid[mb][n8][q0 + 1] * INV254;
                    s = fmaf(v0 * sv.x, u.x, s);
                    s = fmaf(v1 * sv.y, u.y, s);
                    acc_hi[mb][n8][q0] = 0;     acc_mid[mb][n8][q0] = 0;
                    acc_hi[mb][n8][q0 + 1] = 0; acc_mid[mb][n8][q0 + 1] = 0;
                }
                s *= sa;
                s += __shfl_xor_sync(0xffffffffu, s, 1);
                s += __shfl_xor_sync(0xffffffffu, s, 2);
                if ((lane & 3) == 0)
                    slog[(r * 2 + (wid & 1)) * TILE + row] = s;
            }
        __syncthreads();
    }

    // --- softmax(5), preds, loss -------------------------------------------
    float* slossp = (float*)(smem + SM_LOSS);
    if (tid < TILE) {
        const int row = n0 + tid;
        float lg[RR];
#pragma unroll
        for (int r = 0; r < RR; ++r)
            lg[r] = slog[(r * 2 + 0) * TILE + tid] + slog[(r * 2 + 1) * TILE + tid];
        float m = lg[0];
#pragma unroll
        for (int j = 1; j < RR; ++j) m = fmaxf(m, lg[j]);
        float se = 0.f, pe = 0.f;
#pragma unroll
        for (int j = 0; j < RR; ++j) {
            float ex = expf(lg[j] - m);
            se += ex;
            pe += (float)(j + 1) * ex;
        }
        preds[row] = pe / se;
        int lab = rels[row];
        float ll = lg[0];
#pragma unroll
        for (int j = 1; j < RR; ++j) ll = (lab == j) ? lg[j] : ll;
        slossp[tid] = -(ll - m - logf(se));
    }
    __syncthreads();
#pragma unroll
    for (int off = 64; off > 0; off >>= 1) {
        if (tid < off) slossp[tid] += slossp[tid + off];
        __syncthreads();
    }
    if (tid == 0) g_partial[blockIdx.x] = slossp[0];
}

// ---------------------------------------------------------------------------
__global__ void finalize_kernel(float* __restrict__ out, int has_loss) {
    __shared__ float s[256];
    int tid = threadIdx.x;
    float v = 0.f;
    for (int i = tid; i < NBLK; i += 256) v += g_partial[i];
    s[tid] = v;
    __syncthreads();
#pragma unroll
    for (int off = 128; off > 0; off >>= 1) {
        if (tid < off) s[tid] += s[tid + off];
        __syncthreads();
    }
    if (tid == 0 && has_loss) out[0] = s[0] / (float)NROWS;
}

// ---------------------------------------------------------------------------
extern "C" void kernel_launch(void* const* d_in, const int* in_sizes, int n_in,
                              void* d_out, int out_size) {
    const float* e1         = (const float*)d_in[0];
    const float* e2         = (const float*)d_in[1];
    const float* rel_embeds = (const float*)d_in[2];
    const float* ws         = (const float*)d_in[3];
    const int*   rels       = (const int*)d_in[4];
    float* out = (float*)d_out;

    int loss_off = out_size - NROWS;
    if (loss_off < 0) loss_off = 0;
    float* preds = out + loss_off;

    cudaFuncSetAttribute(bilinear_imma_kernel,
                         cudaFuncAttributeMaxDynamicSharedMemorySize, SM_TOTAL);

    prep_kernel<<<RR * DD, 32>>>(rel_embeds, ws);
    bilinear_imma_kernel<<<NBLK, NTHR, SM_TOTAL>>>(e1, e2, rels, preds);
    finalize_kernel<<<1, 256>>>(out, loss_off > 0 ? 1 : 0);
}

// round 9
// speedup vs baseline: 1.0006x; 1.0006x over previous
#include <cuda_runtime.h>
#include <cuda_bf16.h>
#include <stdint.h>

#define NROWS 131072
#define DD    128
#define RR    5
#define WW    16
#define TILE  128
#define NBLK  (NROWS/TILE)
#define NTHR  256

#define E1S   132      // float stride for e1 tile (row-major)
#define AST   144      // byte stride for int8 A rows (conflict-free quads)

// dynamic smem layout (bytes)
#define SM_A0    0
#define SM_A1    18432
#define SM_SA    36864
#define SM_SB    37376
#define SM_B     40960
#define SM_BSZ   32768
#define SM_E1    106496
#define SM_LOG   174080
#define SM_LOSS  179200
#define SM_TOTAL 179712

#define INV254 (1.0f/254.0f)

__device__ __align__(256) uint32_t g_B[RR * 8192];  // fragment-ordered int8 B, 2 levels
__device__ float g_sb[RR * DD];                     // per-(r, d-column) scales
__device__ float g_partial[NBLK];

// ---------------------------------------------------------------------------
__device__ __forceinline__ uint32_t smem_u32(const void* p) {
    uint32_t a;
    asm("{ .reg .u64 t; cvta.to.shared.u64 t, %1; cvt.u32.u64 %0, t; }" : "=r"(a) : "l"(p));
    return a;
}
__device__ __forceinline__ void cp16(uint32_t dst, const void* src) {
    asm volatile("cp.async.cg.shared.global [%0], [%1], 16;" :: "r"(dst), "l"(src));
}
#define CP_COMMIT() asm volatile("cp.async.commit_group;" ::: "memory")
#define CP_WAIT(N)  asm volatile("cp.async.wait_group %0;" :: "n"(N) : "memory")

#define LDSU32(r, a) asm volatile("ld.shared.b32 %0, [%1];" : "=r"(r) : "r"(a))
#define LDSV2(r0, r1, a) \
    asm volatile("ld.shared.v2.b32 {%0,%1}, [%2];" : "=r"(r0), "=r"(r1) : "r"(a))

#define IMMA16832(D, A, B0, B1) \
    asm volatile("mma.sync.aligned.m16n8k32.row.col.s32.s8.s8.s32 " \
        "{%0,%1,%2,%3},{%4,%5,%6,%7},{%8,%9},{%0,%1,%2,%3};" \
        : "+r"((D)[0]), "+r"((D)[1]), "+r"((D)[2]), "+r"((D)[3]) \
        : "r"((A)[0]), "r"((A)[1]), "r"((A)[2]), "r"((A)[3]), "r"(B0), "r"(B1))

__device__ __forceinline__ uint32_t pack4(int a, int b, int c, int d) {
    return (uint32_t)(a & 255) | ((uint32_t)(b & 255) << 8) |
           ((uint32_t)(c & 255) << 16) | ((uint32_t)(d & 255) << 24);
}

// ---------------------------------------------------------------------------
// prep: one block per (r, d): C_r[d][e] = sum_w ws[w,r]*rel[w][d][e];
// per-column scale s_b = max_e|C|/127; two-level int8 quantize; write
// fragment-ordered so the main kernel's B loads are plain ld.shared.v2.
// ---------------------------------------------------------------------------
__global__ void prep_kernel(const float* __restrict__ rel, const float* __restrict__ ws) {
    const int blk = blockIdx.x;            // 0..639
    const int r = blk >> 7;
    const int d = blk & 127;
    const int t = threadIdx.x;             // e4 = t, covers e = 4t..4t+3

    float c[4];
#pragma unroll
    for (int j = 0; j < 4; ++j) c[j] = 0.f;
#pragma unroll
    for (int w = 0; w < WW; ++w) {
        const float s = ws[w * RR + r];
        const float* p = rel + (size_t)w * DD * DD + d * DD + t * 4;
#pragma unroll
        for (int j = 0; j < 4; ++j) c[j] = fmaf(s, p[j], c[j]);
    }
    float mx = fmaxf(fmaxf(fabsf(c[0]), fabsf(c[1])), fmaxf(fabsf(c[2]), fabsf(c[3])));
#pragma unroll
    for (int off = 16; off > 0; off >>= 1)
        mx = fmaxf(mx, __shfl_xor_sync(0xffffffffu, mx, off));
    const float sb = fmaxf(mx, 1e-20f) / 127.f;
    if (t == 0) g_sb[r * DD + d] = sb;
    const float inv = 1.f / sb;

    int hi[4], lo[4];
#pragma unroll
    for (int j = 0; j < 4; ++j) {
        float q = c[j] * inv;
        int h = __float2int_rn(q);
        int l = __float2int_rn((q - (float)h) * 254.f);
        hi[j] = h; lo[j] = l;
    }
    const uint32_t phi = pack4(hi[0], hi[1], hi[2], hi[3]);
    const uint32_t plo = pack4(lo[0], lo[1], lo[2], lo[3]);

    // fragment ordering: u32 index = (((r*2+lvl)*16 + n8)*4 + kb)*64 + lane*2 + reg
    const int kb = t >> 3, eb4 = t & 7, reg = eb4 >> 2;
    const int lane = (d & 7) * 4 + (eb4 & 3);
    const int n8 = d >> 3;
    g_B[(((r * 2 + 0) * 16 + n8) * 4 + kb) * 64 + lane * 2 + reg] = phi;
    g_B[(((r * 2 + 1) * 16 + n8) * 4 + kb) * 64 + lane * 2 + reg] = plo;
}

// ---------------------------------------------------------------------------
__device__ __forceinline__ void load_B_stage(uint32_t sb_, int tid, int st) {
    const char* src = (const char*)g_B + (size_t)st * 32768;
    uint32_t dbase = sb_ + SM_B + (uint32_t)(st & 1) * SM_BSZ;
#pragma unroll
    for (int j = 0; j < 8; ++j) {
        int i = tid + j * NTHR;            // 0..2047 16B chunks
        cp16(dbase + i * 16, src + i * 16);
    }
}

__global__ __launch_bounds__(NTHR, 1) void bilinear_imma_kernel(
    const float* __restrict__ e1g, const float* __restrict__ e2g,
    const int* __restrict__ rels, float* __restrict__ preds) {

    extern __shared__ char smem[];
    const uint32_t sb = smem_u32(smem);
    const int tid  = threadIdx.x;
    const int lane = tid & 31;
    const int wid  = tid >> 5;
    const int n0   = blockIdx.x * TILE;

    // prefetch B stage 0
    load_B_stage(sb, tid, 0);
    CP_COMMIT();

    // s_b table -> smem
    float* ssb = (float*)(smem + SM_SB);
    for (int i = tid; i < RR * DD; i += NTHR) ssb[i] = g_sb[i];

    // --- A build: two-level int8 quantize of E2 tile (per-row scale) -------
    {
        const int row = tid >> 1, half = tid & 1;
        const float4* e2r = (const float4*)(e2g + (size_t)(n0 + row) * DD) + half * 16;
        float mx = 0.f;
#pragma unroll
        for (int q = 0; q < 16; ++q) {
            float4 t = e2r[q];
            mx = fmaxf(mx, fmaxf(fmaxf(fabsf(t.x), fabsf(t.y)), fmaxf(fabsf(t.z), fabsf(t.w))));
        }
        mx = fmaxf(mx, __shfl_xor_sync(0xffffffffu, mx, 1));
        const float sa = fmaxf(mx, 1e-20f) / 127.f;
        const float inv = 1.f / sa;
        float* ssa = (float*)(smem + SM_SA);
        if (!half) ssa[row] = sa;
        char* pA0 = smem + SM_A0 + row * AST + half * 64;
        char* pA1 = smem + SM_A1 + row * AST + half * 64;
#pragma unroll
        for (int q = 0; q < 16; ++q) {
            float4 t = e2r[q];
            float qx = t.x * inv, qy = t.y * inv, qz = t.z * inv, qw = t.w * inv;
            int h0 = __float2int_rn(qx), h1 = __float2int_rn(qy);
            int h2 = __float2int_rn(qz), h3 = __float2int_rn(qw);
            int l0 = __float2int_rn((qx - (float)h0) * 254.f);
            int l1 = __float2int_rn((qy - (float)h1) * 254.f);
            int l2 = __float2int_rn((qz - (float)h2) * 254.f);
            int l3 = __float2int_rn((qw - (float)h3) * 254.f);
            *(uint32_t*)(pA0 + q * 4) = pack4(h0, h1, h2, h3);
            *(uint32_t*)(pA1 + q * 4) = pack4(l0, l1, l2, l3);
        }
        // e1 tile -> smem row-major
        const float4* e1r = (const float4*)(e1g + (size_t)(n0 + row) * DD) + half * 16;
        float4* d1 = (float4*)((float*)(smem + SM_E1) + row * E1S) + half * 16;
#pragma unroll
        for (int q = 0; q < 16; ++q) d1[q] = e1r[q];
    }
    __syncthreads();

    // warp tile: rows [(wid>>1)*32, +32), cols [(wid&1)*64, +64)
    const int rowbase = (wid >> 1) * 32;
    const int chalf   = (wid & 1) * 64;
    const uint32_t aBase = sb + SM_A0 + (uint32_t)(rowbase + (lane >> 2)) * AST + (lane & 3) * 4;
    const uint32_t bWarp = (uint32_t)(wid & 1) * 8192 + (uint32_t)lane * 8;

    int acc_hi[2][8][4], acc_mid[2][8][4];
#pragma unroll
    for (int mb = 0; mb < 2; ++mb)
#pragma unroll
        for (int n8 = 0; n8 < 8; ++n8)
#pragma unroll
            for (int q = 0; q < 4; ++q) { acc_hi[mb][n8][q] = 0; acc_mid[mb][n8][q] = 0; }

    float* slog = (float*)(smem + SM_LOG);
    const float* se1 = (const float*)(smem + SM_E1);
    const float* ssa = (const float*)(smem + SM_SA);

    for (int r = 0; r < RR; ++r) {
        if (r < RR - 1) {
            load_B_stage(sb, tid, r + 1);
            CP_COMMIT();
            CP_WAIT(1);
        } else {
            CP_WAIT(0);
        }
        __syncthreads();

        const uint32_t bb = sb + SM_B + (uint32_t)(r & 1) * SM_BSZ + bWarp;

#pragma unroll
        for (int kb = 0; kb < 4; ++kb) {
            uint32_t ahi[2][4], alo[2][4];
#pragma unroll
            for (int mb = 0; mb < 2; ++mb) {
                const uint32_t ab = aBase + mb * (16 * AST) + kb * 32;
                LDSU32(ahi[mb][0], ab);
                LDSU32(ahi[mb][1], ab + 8 * AST);
                LDSU32(ahi[mb][2], ab + 16);
                LDSU32(ahi[mb][3], ab + 8 * AST + 16);
                LDSU32(alo[mb][0], ab + 18432);
                LDSU32(alo[mb][1], ab + 18432 + 8 * AST);
                LDSU32(alo[mb][2], ab + 18432 + 16);
                LDSU32(alo[mb][3], ab + 18432 + 8 * AST + 16);
            }
#pragma unroll
            for (int n8 = 0; n8 < 8; ++n8) {
                uint32_t bh0, bh1, bl0, bl1;
                const uint32_t ba = bb + (uint32_t)(n8 * 4 + kb) * 256;
                LDSV2(bh0, bh1, ba);
                LDSV2(bl0, bl1, ba + 16384);
#pragma unroll
                for (int mb = 0; mb < 2; ++mb) {
                    IMMA16832(acc_hi[mb][n8],  ahi[mb], bh0, bh1);
                    IMMA16832(acc_mid[mb][n8], ahi[mb], bl0, bl1);
                    IMMA16832(acc_mid[mb][n8], alo[mb], bh0, bh1);
                }
            }
        }

        // epilogue for this r: dequant + dot with e1, per-row scale folded out
        const float* sbp = ssb + r * DD + chalf + (lane & 3) * 2;
#pragma unroll
        for (int mb = 0; mb < 2; ++mb)
#pragma unroll
            for (int rs = 0; rs < 2; ++rs) {
                const int row = rowbase + mb * 16 + rs * 8 + (lane >> 2);
                const float sa = ssa[row];
                const float* er = se1 + row * E1S + chalf + (lane & 3) * 2;
                float s = 0.f;
#pragma unroll
                for (int n8 = 0; n8 < 8; ++n8) {
                    float2 u  = *(const float2*)(er  + n8 * 8);
                    float2 sv = *(const float2*)(sbp + n8 * 8);
                    const int q0 = rs * 2;
                    float v0 = (float)acc_hi[mb][n8][q0]     + (float)acc_mid[mb][n8][q0]     * INV254;
                    float v1 = (float)acc_hi[mb][n8][q0 + 1] + (float)acc_mid[mb][n8][q0 + 1] * INV254;
                    s = fmaf(v0 * sv.x, u.x, s);
                    s = fmaf(v1 * sv.y, u.y, s);
                    acc_hi[mb][n8][q0] = 0;     acc_mid[mb][n8][q0] = 0;
                    acc_hi[mb][n8][q0 + 1] = 0; acc_mid[mb][n8][q0 + 1] = 0;
                }
                s *= sa;
                s += __shfl_xor_sync(0xffffffffu, s, 1);
                s += __shfl_xor_sync(0xffffffffu, s, 2);
                if ((lane & 3) == 0)
                    slog[(r * 2 + (wid & 1)) * TILE + row] = s;
            }
        __syncthreads();
    }

    // --- softmax(5), preds, loss -------------------------------------------
    float* slossp = (float*)(smem + SM_LOSS);
    if (tid < TILE) {
        const int row = n0 + tid;
        float lg[RR];
#pragma unroll
        for (int r = 0; r < RR; ++r)
            lg[r] = slog[(r * 2 + 0) * TILE + tid] + slog[(r * 2 + 1) * TILE + tid];
        float m = lg[0];
#pragma unroll
        for (int j = 1; j < RR; ++j) m = fmaxf(m, lg[j]);
        float se = 0.f, pe = 0.f;
#pragma unroll
        for (int j = 0; j < RR; ++j) {
            float ex = expf(lg[j] - m);
            se += ex;
            pe += (float)(j + 1) * ex;
        }
        preds[row] = pe / se;
        int lab = rels[row];
        float ll = lg[0];
#pragma unroll
        for (int j = 1; j < RR; ++j) ll = (lab == j) ? lg[j] : ll;
        slossp[tid] = -(ll - m - logf(se));
    }
    __syncthreads();
#pragma unroll
    for (int off = 64; off > 0; off >>= 1) {
        if (tid < off) slossp[tid] += slossp[tid + off];
        __syncthreads();
    }
    if (tid == 0) g_partial[blockIdx.x] = slossp[0];
}

// ---------------------------------------------------------------------------
__global__ void finalize_kernel(float* __restrict__ out, int has_loss) {
    __shared__ float s[256];
    int tid = threadIdx.x;
    float v = 0.f;
    for (int i = tid; i < NBLK; i += 256) v += g_partial[i];
    s[tid] = v;
    __syncthreads();
#pragma unroll
    for (int off = 128; off > 0; off >>= 1) {
        if (tid < off) s[tid] += s[tid + off];
        __syncthreads();
    }
    if (tid == 0 && has_loss) out[0] = s[0] / (float)NROWS;
}

// ---------------------------------------------------------------------------
extern "C" void kernel_launch(void* const* d_in, const int* in_sizes, int n_in,
                              void* d_out, int out_size) {
    const float* e1         = (const float*)d_in[0];
    const float* e2         = (const float*)d_in[1];
    const float* rel_embeds = (const float*)d_in[2];
    const float* ws         = (const float*)d_in[3];
    const int*   rels       = (const int*)d_in[4];
    float* out = (float*)d_out;

    int loss_off = out_size - NROWS;
    if (loss_off < 0) loss_off = 0;
    float* preds = out + loss_off;

    cudaFuncSetAttribute(bilinear_imma_kernel,
                         cudaFuncAttributeMaxDynamicSharedMemorySize, SM_TOTAL);

    prep_kernel<<<RR * DD, 32>>>(rel_embeds, ws);
    bilinear_imma_kernel<<<NBLK, NTHR, SM_TOTAL>>>(e1, e2, rels, preds);
    finalize_kernel<<<1, 256>>>(out, loss_off > 0 ? 1 : 0);
}

// round 10
// speedup vs baseline: 1.0008x; 1.0002x over previous
#include <cuda_runtime.h>
#include <cuda_bf16.h>
#include <stdint.h>

#define NROWS 131072
#define DD    128
#define RR    5
#define WW    16
#define TILE  128
#define NBLK  (NROWS/TILE)
#define NTHR  256

#define E1S   132      // float stride for e1 tile (row-major)
#define AST   144      // byte stride for int8 A rows (conflict-free quads)

// dynamic smem layout (bytes)
#define SM_A0    0
#define SM_A1    18432
#define SM_SA    36864
#define SM_SB    37376
#define SM_B     40960
#define SM_BSZ   32768
#define SM_E1    106496
#define SM_LOG   174080
#define SM_LOSS  179200
#define SM_TOTAL 179712

#define INV254 (1.0f/254.0f)

__device__ __align__(256) uint32_t g_B[RR * 8192];  // fragment-ordered int8 B, 2 levels
__device__ float g_sb[RR * DD];                     // per-(r, d-column) scales
__device__ float g_partial[NBLK];

// ---------------------------------------------------------------------------
__device__ __forceinline__ uint32_t smem_u32(const void* p) {
    uint32_t a;
    asm("{ .reg .u64 t; cvta.to.shared.u64 t, %1; cvt.u32.u64 %0, t; }" : "=r"(a) : "l"(p));
    return a;
}
__device__ __forceinline__ void cp16(uint32_t dst, const void* src) {
    asm volatile("cp.async.cg.shared.global [%0], [%1], 16;" :: "r"(dst), "l"(src));
}
#define CP_COMMIT() asm volatile("cp.async.commit_group;" ::: "memory")
#define CP_WAIT(N)  asm volatile("cp.async.wait_group %0;" :: "n"(N) : "memory")

#define LDSU32(r, a) asm volatile("ld.shared.b32 %0, [%1];" : "=r"(r) : "r"(a))
#define LDSV2(r0, r1, a) \
    asm volatile("ld.shared.v2.b32 {%0,%1}, [%2];" : "=r"(r0), "=r"(r1) : "r"(a))

#define IMMA16832(D, A, B0, B1) \
    asm volatile("mma.sync.aligned.m16n8k32.row.col.s32.s8.s8.s32 " \
        "{%0,%1,%2,%3},{%4,%5,%6,%7},{%8,%9},{%0,%1,%2,%3};" \
        : "+r"((D)[0]), "+r"((D)[1]), "+r"((D)[2]), "+r"((D)[3]) \
        : "r"((A)[0]), "r"((A)[1]), "r"((A)[2]), "r"((A)[3]), "r"(B0), "r"(B1))

__device__ __forceinline__ uint32_t pack4(int a, int b, int c, int d) {
    return (uint32_t)(a & 255) | ((uint32_t)(b & 255) << 8) |
           ((uint32_t)(c & 255) << 16) | ((uint32_t)(d & 255) << 24);
}

// ---------------------------------------------------------------------------
// prep: one block per (r, d): C_r[d][e] = sum_w ws[w,r]*rel[w][d][e];
// per-column scale s_b = max_e|C|/127; two-level int8 quantize; write
// fragment-ordered so the main kernel's B loads are plain ld.shared.v2.
// ---------------------------------------------------------------------------
__global__ void prep_kernel(const float* __restrict__ rel, const float* __restrict__ ws) {
    const int blk = blockIdx.x;            // 0..639
    const int r = blk >> 7;
    const int d = blk & 127;
    const int t = threadIdx.x;             // e4 = t, covers e = 4t..4t+3

    float c[4];
#pragma unroll
    for (int j = 0; j < 4; ++j) c[j] = 0.f;
#pragma unroll
    for (int w = 0; w < WW; ++w) {
        const float s = ws[w * RR + r];
        const float* p = rel + (size_t)w * DD * DD + d * DD + t * 4;
#pragma unroll
        for (int j = 0; j < 4; ++j) c[j] = fmaf(s, p[j], c[j]);
    }
    float mx = fmaxf(fmaxf(fabsf(c[0]), fabsf(c[1])), fmaxf(fabsf(c[2]), fabsf(c[3])));
#pragma unroll
    for (int off = 16; off > 0; off >>= 1)
        mx = fmaxf(mx, __shfl_xor_sync(0xffffffffu, mx, off));
    const float sb = fmaxf(mx, 1e-20f) / 127.f;
    if (t == 0) g_sb[r * DD + d] = sb;
    const float inv = 1.f / sb;

    int hi[4], lo[4];
#pragma unroll
    for (int j = 0; j < 4; ++j) {
        float q = c[j] * inv;
        int h = __float2int_rn(q);
        int l = __float2int_rn((q - (float)h) * 254.f);
        hi[j] = h; lo[j] = l;
    }
    const uint32_t phi = pack4(hi[0], hi[1], hi[2], hi[3]);
    const uint32_t plo = pack4(lo[0], lo[1], lo[2], lo[3]);

    // fragment ordering: u32 index = (((r*2+lvl)*16 + n8)*4 + kb)*64 + lane*2 + reg
    const int kb = t >> 3, eb4 = t & 7, reg = eb4 >> 2;
    const int lane = (d & 7) * 4 + (eb4 & 3);
    const int n8 = d >> 3;
    g_B[(((r * 2 + 0) * 16 + n8) * 4 + kb) * 64 + lane * 2 + reg] = phi;
    g_B[(((r * 2 + 1) * 16 + n8) * 4 + kb) * 64 + lane * 2 + reg] = plo;
}

// ---------------------------------------------------------------------------
__device__ __forceinline__ void load_B_stage(uint32_t sb_, int tid, int st) {
    const char* src = (const char*)g_B + (size_t)st * 32768;
    uint32_t dbase = sb_ + SM_B + (uint32_t)(st & 1) * SM_BSZ;
#pragma unroll
    for (int j = 0; j < 8; ++j) {
        int i = tid + j * NTHR;            // 0..2047 16B chunks
        cp16(dbase + i * 16, src + i * 16);
    }
}

__global__ __launch_bounds__(NTHR, 1) void bilinear_imma_kernel(
    const float* __restrict__ e1g, const float* __restrict__ e2g,
    const int* __restrict__ rels, float* __restrict__ preds) {

    extern __shared__ char smem[];
    const uint32_t sb = smem_u32(smem);
    const int tid  = threadIdx.x;
    const int lane = tid & 31;
    const int wid  = tid >> 5;
    const int n0   = blockIdx.x * TILE;

    // prefetch B stage 0
    load_B_stage(sb, tid, 0);
    CP_COMMIT();

    // s_b table -> smem
    float* ssb = (float*)(smem + SM_SB);
    for (int i = tid; i < RR * DD; i += NTHR) ssb[i] = g_sb[i];

    // --- A build: two-level int8 quantize of E2 tile (per-row scale) -------
    {
        const int row = tid >> 1, half = tid & 1;
        const float4* e2r = (const float4*)(e2g + (size_t)(n0 + row) * DD) + half * 16;
        float mx = 0.f;
#pragma unroll
        for (int q = 0; q < 16; ++q) {
            float4 t = e2r[q];
            mx = fmaxf(mx, fmaxf(fmaxf(fabsf(t.x), fabsf(t.y)), fmaxf(fabsf(t.z), fabsf(t.w))));
        }
        mx = fmaxf(mx, __shfl_xor_sync(0xffffffffu, mx, 1));
        const float sa = fmaxf(mx, 1e-20f) / 127.f;
        const float inv = 1.f / sa;
        float* ssa = (float*)(smem + SM_SA);
        if (!half) ssa[row] = sa;
        char* pA0 = smem + SM_A0 + row * AST + half * 64;
        char* pA1 = smem + SM_A1 + row * AST + half * 64;
#pragma unroll
        for (int q = 0; q < 16; ++q) {
            float4 t = e2r[q];
            float qx = t.x * inv, qy = t.y * inv, qz = t.z * inv, qw = t.w * inv;
            int h0 = __float2int_rn(qx), h1 = __float2int_rn(qy);
            int h2 = __float2int_rn(qz), h3 = __float2int_rn(qw);
            int l0 = __float2int_rn((qx - (float)h0) * 254.f);
            int l1 = __float2int_rn((qy - (float)h1) * 254.f);
            int l2 = __float2int_rn((qz - (float)h2) * 254.f);
            int l3 = __float2int_rn((qw - (float)h3) * 254.f);
            *(uint32_t*)(pA0 + q * 4) = pack4(h0, h1, h2, h3);
            *(uint32_t*)(pA1 + q * 4) = pack4(l0, l1, l2, l3);
        }
        // e1 tile -> smem row-major
        const float4* e1r = (const float4*)(e1g + (size_t)(n0 + row) * DD) + half * 16;
        float4* d1 = (float4*)((float*)(smem + SM_E1) + row * E1S) + half * 16;
#pragma unroll
        for (int q = 0; q < 16; ++q) d1[q] = e1r[q];
    }
    __syncthreads();

    // warp tile: rows [(wid>>1)*32, +32), cols [(wid&1)*64, +64)
    const int rowbase = (wid >> 1) * 32;
    const int chalf   = (wid & 1) * 64;
    const uint32_t aBase = sb + SM_A0 + (uint32_t)(rowbase + (lane >> 2)) * AST + (lane & 3) * 4;
    const uint32_t bWarp = (uint32_t)(wid & 1) * 8192 + (uint32_t)lane * 8;

    int acc_hi[2][8][4], acc_mid[2][8][4];
#pragma unroll
    for (int mb = 0; mb < 2; ++mb)
#pragma unroll
        for (int n8 = 0; n8 < 8; ++n8)
#pragma unroll
            for (int q = 0; q < 4; ++q) { acc_hi[mb][n8][q] = 0; acc_mid[mb][n8][q] = 0; }

    float* slog = (float*)(smem + SM_LOG);
    const float* se1 = (const float*)(smem + SM_E1);
    const float* ssa = (const float*)(smem + SM_SA);

    for (int r = 0; r < RR; ++r) {
        if (r < RR - 1) {
            load_B_stage(sb, tid, r + 1);
            CP_COMMIT();
            CP_WAIT(1);
        } else {
            CP_WAIT(0);
        }
        __syncthreads();

        const uint32_t bb = sb + SM_B + (uint32_t)(r & 1) * SM_BSZ + bWarp;

#pragma unroll
        for (int kb = 0; kb < 4; ++kb) {
            uint32_t ahi[2][4], alo[2][4];
#pragma unroll
            for (int mb = 0; mb < 2; ++mb) {
                const uint32_t ab = aBase + mb * (16 * AST) + kb * 32;
                LDSU32(ahi[mb][0], ab);
                LDSU32(ahi[mb][1], ab + 8 * AST);
                LDSU32(ahi[mb][2], ab + 16);
                LDSU32(ahi[mb][3], ab + 8 * AST + 16);
                LDSU32(alo[mb][0], ab + 18432);
                LDSU32(alo[mb][1], ab + 18432 + 8 * AST);
                LDSU32(alo[mb][2], ab + 18432 + 16);
                LDSU32(alo[mb][3], ab + 18432 + 8 * AST + 16);
            }
#pragma unroll
            for (int n8 = 0; n8 < 8; ++n8) {
                uint32_t bh0, bh1, bl0, bl1;
                const uint32_t ba = bb + (uint32_t)(n8 * 4 + kb) * 256;
                LDSV2(bh0, bh1, ba);
                LDSV2(bl0, bl1, ba + 16384);
#pragma unroll
                for (int mb = 0; mb < 2; ++mb) {
                    IMMA16832(acc_hi[mb][n8],  ahi[mb], bh0, bh1);
                    IMMA16832(acc_mid[mb][n8], ahi[mb], bl0, bl1);
                    IMMA16832(acc_mid[mb][n8], alo[mb], bh0, bh1);
                }
            }
        }

        // epilogue for this r: dequant + dot with e1, per-row scale folded out
        const float* sbp = ssb + r * DD + chalf + (lane & 3) * 2;
#pragma unroll
        for (int mb = 0; mb < 2; ++mb)
#pragma unroll
            for (int rs = 0; rs < 2; ++rs) {
                const int row = rowbase + mb * 16 + rs * 8 + (lane >> 2);
                const float sa = ssa[row];
                const float* er = se1 + row * E1S + chalf + (lane & 3) * 2;
                float s = 0.f;
#pragma unroll
                for (int n8 = 0; n8 < 8; ++n8) {
                    float2 u  = *(const float2*)(er  + n8 * 8);
                    float2 sv = *(const float2*)(sbp + n8 * 8);
                    const int q0 = rs * 2;
                    float v0 = (float)acc_hi[mb][n8][q0]     + (float)acc_mid[mb][n8][q0]     * INV254;
                    float v1 = (float)acc_hi[mb][n8][q0 + 1] + (float)acc_mid[mb][n8][q0 + 1] * INV254;
                    s = fmaf(v0 * sv.x, u.x, s);
                    s = fmaf(v1 * sv.y, u.y, s);
                    acc_hi[mb][n8][q0] = 0;     acc_mid[mb][n8][q0] = 0;
                    acc_hi[mb][n8][q0 + 1] = 0; acc_mid[mb][n8][q0 + 1] = 0;
                }
                s *= sa;
                s += __shfl_xor_sync(0xffffffffu, s, 1);
                s += __shfl_xor_sync(0xffffffffu, s, 2);
                if ((lane & 3) == 0)
                    slog[(r * 2 + (wid & 1)) * TILE + row] = s;
            }
        __syncthreads();
    }

    // --- softmax(5), preds, loss -------------------------------------------
    float* slossp = (float*)(smem + SM_LOSS);
    if (tid < TILE) {
        const int row = n0 + tid;
        float lg[RR];
#pragma unroll
        for (int r = 0; r < RR; ++r)
            lg[r] = slog[(r * 2 + 0) * TILE + tid] + slog[(r * 2 + 1) * TILE + tid];
        float m = lg[0];
#pragma unroll
        for (int j = 1; j < RR; ++j) m = fmaxf(m, lg[j]);
        float se = 0.f, pe = 0.f;
#pragma unroll
        for (int j = 0; j < RR; ++j) {
            float ex = expf(lg[j] - m);
            se += ex;
            pe += (float)(j + 1) * ex;
        }
        preds[row] = pe / se;
        int lab = rels[row];
        float ll = lg[0];
#pragma unroll
        for (int j = 1; j < RR; ++j) ll = (lab == j) ? lg[j] : ll;
        slossp[tid] = -(ll - m - logf(se));
    }
    __syncthreads();
#pragma unroll
    for (int off = 64; off > 0; off >>= 1) {
        if (tid < off) slossp[tid] += slossp[tid + off];
        __syncthreads();
    }
    if (tid == 0) g_partial[blockIdx.x] = slossp[0];
}

// ---------------------------------------------------------------------------
__global__ void finalize_kernel(float* __restrict__ out, int has_loss) {
    __shared__ float s[256];
    int tid = threadIdx.x;
    float v = 0.f;
    for (int i = tid; i < NBLK; i += 256) v += g_partial[i];
    s[tid] = v;
    __syncthreads();
#pragma unroll
    for (int off = 128; off > 0; off >>= 1) {
        if (tid < off) s[tid] += s[tid + off];
        __syncthreads();
    }
    if (tid == 0 && has_loss) out[0] = s[0] / (float)NROWS;
}

// ---------------------------------------------------------------------------
extern "C" void kernel_launch(void* const* d_in, const int* in_sizes, int n_in,
                              void* d_out, int out_size) {
    const float* e1         = (const float*)d_in[0];
    const float* e2         = (const float*)d_in[1];
    const float* rel_embeds = (const float*)d_in[2];
    const float* ws         = (const float*)d_in[3];
    const int*   rels       = (const int*)d_in[4];
    float* out = (float*)d_out;

    int loss_off = out_size - NROWS;
    if (loss_off < 0) loss_off = 0;
    float* preds = out + loss_off;

    cudaFuncSetAttribute(bilinear_imma_kernel,
                         cudaFuncAttributeMaxDynamicSharedMemorySize, SM_TOTAL);

    prep_kernel<<<RR * DD, 32>>>(rel_embeds, ws);
    bilinear_imma_kernel<<<NBLK, NTHR, SM_TOTAL>>>(e1, e2, rels, preds);
    finalize_kernel<<<1, 256>>>(out, loss_off > 0 ? 1 : 0);
}